// round 12
// baseline (speedup 1.0000x reference)
#include <cuda_runtime.h>
#include <cuda_bf16.h>
#include <cuda_fp16.h>
#include <cstdint>

// Problem constants (fixed shapes)
#define BB    2
#define NN    20000
#define EE    200000
#define INF   256
#define OUTF  32
#define HEADS 4
#define HDIM  (OUTF * HEADS)   // 128
#define NEG_SLOPE 0.2f

// ---------------- device scratch ----------------
// CRITICAL: symbols are ONLY referenced inside device code (host-side decay of
// __device__ symbols is the GB300 ATS silent-corruption trap from rounds 1-6).
__device__ float  g_wf [HDIM * INF];                // W tf32 bits, FRAGMENT-SWIZZLED
__device__ float  g_af [2 * OUTF];                  // a (fp32)
__device__ __half g_h  [(size_t)BB * NN * HDIM];    // h = x@W^T (fp16, agg-only)
__device__ float  g_ssrc[(size_t)BB * NN * HEADS];  // per-node src score (fp32)
__device__ float  g_sdst[(size_t)BB * NN * HEADS];  // per-node dst score (fp32)
__device__ float  g_aw [(size_t)BB * NN * HEADS];   // aw * 0.25
__device__ int    g_last[NN];
__device__ int    g_src [EE];
__device__ int    g_dst [EE];
__device__ int    g_bad_int;
__device__ int    g_odd_nonzero;
__device__ int    g_is_bf16;

__device__ __forceinline__ uint32_t f2tf32(float f) {
    uint32_t r;
    asm("cvt.rna.tf32.f32 %0, %1;" : "=r"(r) : "f"(f));
    return r;
}

#define CP_ASYNC16(smem_u32, gptr) \
    asm volatile("cp.async.cg.shared.global [%0], [%1], 16;" \
                 :: "r"(smem_u32), "l"(gptr))
#define CP_COMMIT() asm volatile("cp.async.commit_group;" ::: "memory")
#define CP_WAIT0()  asm volatile("cp.async.wait_group 0;" ::: "memory")

// ---------------- kernel 1: init + both dtype probes (fused) ---------------
// Block 0: x fp32-vs-bf16 ballot. Block 1: edge-layout ballot over 4096 words.
// Overwrite semantics via __syncthreads_count — safe under graph replay.
__global__ void init_probe_kernel(float* __restrict__ out, int out_size,
                                  const unsigned* __restrict__ xw,
                                  const int* __restrict__ ew) {
    int gid = blockIdx.x * blockDim.x + threadIdx.x;
    if (gid < out_size) out[gid] = 0.0f;
    if (gid < NN)       g_last[gid] = -1;

    if (blockIdx.x == 0) {
        bool all_ok = true;
        for (int j = 0; j < 16; j++) {
            unsigned v = xw[threadIdx.x * 16 + j];
            unsigned lo = v & 0xFFFFu, hi = v >> 16;
            unsigned el = (lo >> 7) & 0xFF, eh = (hi >> 7) & 0xFF;
            bool okl = (lo & 0x7FFF) == 0 || (el >= 100 && el <= 140);
            bool okh = (hi & 0x7FFF) == 0 || (eh >= 100 && eh <= 140);
            all_ok &= (okl && okh);
        }
        int cnt = __syncthreads_count(all_ok);
        if (threadIdx.x == 0) g_is_bf16 = (cnt > 128) ? 1 : 0;
    } else if (blockIdx.x == 1) {
        bool bad = false, oddnz = false;
        for (int j = 0; j < 16; j++) {
            int i = threadIdx.x * 16 + j;
            int v = ew[i];
            if (v < 0 || v >= NN)  bad = true;
            if ((i & 1) && v != 0) oddnz = true;
        }
        int cbad = __syncthreads_count(bad);
        int codd = __syncthreads_count(oddnz);
        if (threadIdx.x == 0) {
            g_bad_int     = (cbad > 0) ? 1 : 0;
            g_odd_nonzero = (codd > 0) ? 1 : 0;
        }
    }
}

// ---------------- kernel 2: materialize W (tf32, fragment-swizzled) + a ----
// Swizzle: for W[n][k]: n_blk=n>>3, g=n&7, kstep=k>>3, t=k&3, h2=(k>>2)&1
//   g_wf[ ((n_blk*32 + kstep)*32 + g*4 + t)*2 + h2 ] = tf32(W[n][k])
// GEMM reads float2 (b0=k+t, b1=k+t+4) at index (n_blk*32+kstep)*32 + lane.
__global__ void fconv_all_kernel(const void* __restrict__ Wraw,
                                 const void* __restrict__ araw) {
    int i = blockIdx.x * blockDim.x + threadIdx.x;
    bool bf = (g_is_bf16 != 0);
    if (i < HDIM * INF) {
        float v = bf ? __bfloat162float(((const __nv_bfloat16*)Wraw)[i])
                     : ((const float*)Wraw)[i];
        int n = i >> 8, k = i & 255;
        int n_blk = n >> 3, g = n & 7;
        int kstep = k >> 3, t = k & 3, h2 = (k >> 2) & 1;
        int dst = ((n_blk * 32 + kstep) * 32 + g * 4 + t) * 2 + h2;
        g_wf[dst] = __uint_as_float(f2tf32(v));
    } else if (i < HDIM * INF + 2 * OUTF) {
        int j = i - HDIM * INF;
        float v = bf ? __bfloat162float(((const __nv_bfloat16*)araw)[j])
                     : ((const float*)araw)[j];
        g_af[j] = v;
    }
}

// ---------------- kernel 3: convert indices + last-edge (fused) ------------
__global__ void convert_lastedge_kernel(const void* __restrict__ raw) {
    int e = blockIdx.x * blockDim.x + threadIdx.x;
    if (e >= EE) return;
    int s, d;
    if (g_bad_int) {                 // float32 layout
        const float* p = (const float*)raw;
        s = (int)p[e];  d = (int)p[EE + e];
    } else if (g_odd_nonzero) {      // int32 layout
        const int* p = (const int*)raw;
        s = p[e];       d = p[EE + e];
    } else {                         // int64 layout
        const long long* p = (const long long*)raw;
        s = (int)p[e];  d = (int)p[EE + e];
    }
    s = min(max(s, 0), NN - 1);
    d = min(max(d, 0), NN - 1);
    g_src[e] = s;
    g_dst[e] = d;
    atomicMax(&g_last[s], e);
}

// ---------------- kernel 4: pipelined tf32 GEMM, B-from-global -------------
// BM=64 x BN=128 (full width) per block, grid 625. BK=32, 2-stage cp.async A.
// 8 warps: mw=warp&3 (16-row quad), nh2=warp>>2 (64-col half = 2 heads).
// B fragments: one coalesced float2 __ldg per MMA from swizzled g_wf (L1-hot).
// Epilogue: fp16 h store + fused per-node score dots (fp32) via shfl.
#define BM 64
#define BK 32
#define SSTRIDE 36
__global__ __launch_bounds__(256) void gemm_tf32(const void* __restrict__ xraw) {
    __shared__ float As[2][BM * SSTRIDE];   // 2 x 9.2 KB

    const int tid  = threadIdx.x;
    const int lane = tid & 31;
    const int g    = lane >> 2;        // 0..7
    const int t    = lane & 3;         // 0..3
    const int warp = tid >> 5;
    const int mw   = warp & 3;
    const int nh2  = warp >> 2;        // 0 or 1 (cols nh2*64 .. +63)
    const int m0   = blockIdx.x * BM;
    const bool is_bf16 = (g_is_bf16 != 0);

    const int pr = tid >> 3;           // 0..31
    const int pc = (tid & 7) * 4;      // 0..28

    const float2* gw = (const float2*)g_wf;

    float acc[8][4];
    #pragma unroll
    for (int i = 0; i < 8; i++)
        #pragma unroll
        for (int j = 0; j < 4; j++) acc[i][j] = 0.0f;

    auto issue_tile = [&](int k0, int buf) {
        if (!is_bf16) {
            #pragma unroll
            for (int p = 0; p < 2; p++) {
                int r = pr + p * 32;
                uint32_t d = (uint32_t)__cvta_generic_to_shared(
                    &As[buf][r * SSTRIDE + pc]);
                CP_ASYNC16(d, (const float*)xraw + (size_t)(m0 + r) * INF + k0 + pc);
            }
        } else {
            int r = tid >> 2;           // 0..63
            int c = (tid & 3) * 8;      // 0,8,16,24
            uint4 u = *(const uint4*)((const __nv_bfloat16*)xraw +
                                      (size_t)(m0 + r) * INF + k0 + c);
            const __nv_bfloat162* hb = (const __nv_bfloat162*)&u;
            float* dstp = &As[buf][r * SSTRIDE + c];
            #pragma unroll
            for (int j = 0; j < 4; j++) {
                float2 f = __bfloat1622float2(hb[j]);
                dstp[2 * j]     = f.x;
                dstp[2 * j + 1] = f.y;
            }
        }
        CP_COMMIT();
    };

    issue_tile(0, 0);
    int buf = 0;
    for (int i = 0; i < INF / BK; i++) {
        CP_WAIT0();
        __syncthreads();
        if (i < INF / BK - 1) issue_tile((i + 1) * BK, buf ^ 1);

        #pragma unroll
        for (int kk4 = 0; kk4 < BK / 8; kk4++) {
            int kstep = i * (BK / 8) + kk4;
            const float* ap = &As[buf][(mw * 16 + g) * SSTRIDE + kk4 * 8 + t];
            uint32_t a0 = f2tf32(ap[0]);
            uint32_t a1 = f2tf32(ap[8 * SSTRIDE]);
            uint32_t a2 = f2tf32(ap[4]);
            uint32_t a3 = f2tf32(ap[8 * SSTRIDE + 4]);
            #pragma unroll
            for (int nt = 0; nt < 8; nt++) {
                float2 bb = __ldg(&gw[((nh2 * 8 + nt) * 32 + kstep) * 32 + lane]);
                uint32_t b0 = __float_as_uint(bb.x);
                uint32_t b1 = __float_as_uint(bb.y);
                asm volatile(
                    "mma.sync.aligned.m16n8k8.row.col.f32.tf32.tf32.f32 "
                    "{%0,%1,%2,%3}, {%4,%5,%6,%7}, {%8,%9}, {%0,%1,%2,%3};"
                    : "+f"(acc[nt][0]), "+f"(acc[nt][1]),
                      "+f"(acc[nt][2]), "+f"(acc[nt][3])
                    : "r"(a0), "r"(a1), "r"(a2), "r"(a3), "r"(b0), "r"(b1));
            }
        }
        buf ^= 1;
    }

    // Epilogue: fp16 h store + fused scores.
    // D frag: c0=(g,2t) c1=(g,2t+1) c2=(g+8,2t) c3=(g+8,2t+1).
    int mrow = m0 + mw * 16 + g;
    float ss[2][2] = {{0.f,0.f},{0.f,0.f}};   // [head-local][row0/row8]
    float sd[2][2] = {{0.f,0.f},{0.f,0.f}};
    #pragma unroll
    for (int nt = 0; nt < 8; nt++) {
        int hl = nt >> 2;                  // warp's local head (0/1)
        int fl = (nt & 3) * 8 + 2 * t;     // f within head, 0..31
        int ncol = nh2 * 64 + nt * 8 + 2 * t;
        *(__half2*)&g_h[(size_t)mrow * HDIM + ncol] =
            __floats2half2_rn(acc[nt][0], acc[nt][1]);
        *(__half2*)&g_h[(size_t)(mrow + 8) * HDIM + ncol] =
            __floats2half2_rn(acc[nt][2], acc[nt][3]);
        float a0s = g_af[fl],        a1s = g_af[fl + 1];
        float a0d = g_af[OUTF + fl], a1d = g_af[OUTF + fl + 1];
        ss[hl][0] += acc[nt][0] * a0s + acc[nt][1] * a1s;
        sd[hl][0] += acc[nt][0] * a0d + acc[nt][1] * a1d;
        ss[hl][1] += acc[nt][2] * a0s + acc[nt][3] * a1s;
        sd[hl][1] += acc[nt][2] * a0d + acc[nt][3] * a1d;
    }
    #pragma unroll
    for (int off = 1; off < 4; off <<= 1) {
        #pragma unroll
        for (int hl = 0; hl < 2; hl++) {
            ss[hl][0] += __shfl_xor_sync(0xffffffffu, ss[hl][0], off);
            ss[hl][1] += __shfl_xor_sync(0xffffffffu, ss[hl][1], off);
            sd[hl][0] += __shfl_xor_sync(0xffffffffu, sd[hl][0], off);
            sd[hl][1] += __shfl_xor_sync(0xffffffffu, sd[hl][1], off);
        }
    }
    if (t == 0) {
        #pragma unroll
        for (int hl = 0; hl < 2; hl++) {
            int head = nh2 * 2 + hl;
            g_ssrc[mrow * HEADS + head]       = ss[hl][0];
            g_ssrc[(mrow + 8) * HEADS + head] = ss[hl][1];
            g_sdst[mrow * HEADS + head]       = sd[hl][0];
            g_sdst[(mrow + 8) * HEADS + head] = sd[hl][1];
        }
    }
}

// ---------------- kernel 5: aw from last-edge softmax over batch -----------
__global__ void aw_kernel() {
    int gid = blockIdx.x * blockDim.x + threadIdx.x;   // n*HEADS + h
    if (gid >= NN * HEADS) return;
    int hh = gid & (HEADS - 1);
    int n  = gid >> 2;
    int e  = g_last[n];
    float w0 = 0.0f, w1 = 0.0f;
    if (e >= 0) {
        int d = g_dst[e];
        float z0 = g_ssrc[n * HEADS + hh]        + g_sdst[d * HEADS + hh];
        float z1 = g_ssrc[(NN + n) * HEADS + hh] + g_sdst[(NN + d) * HEADS + hh];
        z0 = z0 > 0.0f ? z0 : NEG_SLOPE * z0;
        z1 = z1 > 0.0f ? z1 : NEG_SLOPE * z1;
        float m  = fmaxf(z0, z1);
        float p0 = __expf(z0 - m);
        float p1 = __expf(z1 - m);
        float inv = 1.0f / (p0 + p1);
        w0 = p0 * inv;
        w1 = p1 * inv;
    }
    g_aw[n * HEADS + hh]        = 0.25f * w0;   // fold head-mean
    g_aw[(NN + n) * HEADS + hh] = 0.25f * w1;
}

// ---------------- kernel 6: aggregation (fp16 h), v4 RED into d_out --------
__device__ __forceinline__ void red_add_v4(float* ptr, float4 v) {
    asm volatile("red.global.add.v4.f32 [%0], {%1, %2, %3, %4};"
                 :: "l"(ptr), "f"(v.x), "f"(v.y), "f"(v.z), "f"(v.w)
                 : "memory");
}

__device__ __forceinline__ float4 ldh4(const __half* p) {
    uint2 u = __ldg((const uint2*)p);
    float2 a = __half22float2(*(__half2*)&u.x);
    float2 b = __half22float2(*(__half2*)&u.y);
    return make_float4(a.x, a.y, b.x, b.y);
}

__global__ __launch_bounds__(256) void agg_kernel(float* __restrict__ out) {
    int gid = blockIdx.x * blockDim.x + threadIdx.x;
    if (gid >= EE * BB * (OUTF / 4)) return;
    int f4 = gid & 7;          // 0..7
    int b  = (gid >> 3) & 1;
    int e  = gid >> 4;

    int src = g_src[e];
    int dst = g_dst[e];

    float4 c = *(const float4*)(g_aw + ((size_t)b * NN + src) * HEADS);

    const __half* hp = g_h + ((size_t)b * NN + dst) * HDIM + f4 * 4;
    float4 h0 = ldh4(hp);
    float4 h1 = ldh4(hp + OUTF);
    float4 h2 = ldh4(hp + 2 * OUTF);
    float4 h3 = ldh4(hp + 3 * OUTF);

    float4 v;
    v.x = c.x * h0.x + c.y * h1.x + c.z * h2.x + c.w * h3.x;
    v.y = c.x * h0.y + c.y * h1.y + c.z * h2.y + c.w * h3.y;
    v.z = c.x * h0.z + c.y * h1.z + c.z * h2.z + c.w * h3.z;
    v.w = c.x * h0.w + c.y * h1.w + c.z * h2.w + c.w * h3.w;

    red_add_v4(out + ((size_t)b * NN + src) * OUTF + f4 * 4, v);
}

// ---------------- launch ---------------------------------------------------
extern "C" void kernel_launch(void* const* d_in, const int* in_sizes, int n_in,
                              void* d_out, int out_size) {
    // Rank-based binding: largest -> x, 2nd -> edges, 3rd -> W, smallest -> a
    int order[8];
    int m = n_in < 8 ? n_in : 8;
    for (int i = 0; i < m; i++) order[i] = i;
    for (int i = 0; i < m; i++)
        for (int j = i + 1; j < m; j++)
            if (in_sizes[order[j]] > in_sizes[order[i]]) {
                int t = order[i]; order[i] = order[j]; order[j] = t;
            }
    const void* x  = d_in[m > 0 ? order[0] : 0];
    const void* ei = d_in[m > 1 ? order[1] : 1];
    const void* W  = d_in[m > 2 ? order[2] : 2];
    const void* a  = d_in[m > 3 ? order[3] : 3];

    float* out = (float*)d_out;

    {
        int n = out_size > NN ? out_size : NN;
        init_probe_kernel<<<(n + 255) / 256, 256>>>(out, out_size,
                             (const unsigned*)x, (const int*)ei);         // 1
    }
    fconv_all_kernel<<<(HDIM * INF + 2 * OUTF + 255) / 256, 256>>>(W, a); // 2
    convert_lastedge_kernel<<<(EE + 255) / 256, 256>>>(ei);               // 3
    gemm_tf32<<<(BB * NN) / BM, 256>>>(x);                                // 4 <- profiled
    aw_kernel<<<(NN * HEADS + 255) / 256, 256>>>();                       // 5
    agg_kernel<<<(EE * BB * (OUTF / 4) + 255) / 256, 256>>>(out);         // 6
}

// round 13
// speedup vs baseline: 1.1999x; 1.1999x over previous
#include <cuda_runtime.h>
#include <cuda_bf16.h>
#include <cuda_fp16.h>
#include <cstdint>

// Problem constants (fixed shapes)
#define BB    2
#define NN    20000
#define EE    200000
#define INF   256
#define OUTF  32
#define HEADS 4
#define HDIM  (OUTF * HEADS)   // 128
#define NEG_SLOPE 0.2f
#define NROWS (BB * NN)        // 40000

// ---------------- device scratch ----------------
// CRITICAL: symbols are ONLY referenced inside device code (host-side decay of
// __device__ symbols is the GB300 ATS silent-corruption trap from rounds 1-6).
__device__ float  g_wf [HDIM * INF];                // W tf32 bits, FRAGMENT-SWIZZLED
__device__ float  g_af [2 * OUTF];                  // a (fp32)
__device__ __half g_h  [(size_t)NROWS * HDIM];      // h = x@W^T (fp16, agg-only)
__device__ float  g_ssrc[(size_t)NROWS * HEADS];    // per-node src score (fp32)
__device__ float  g_sdst[(size_t)NROWS * HEADS];    // per-node dst score (fp32)
__device__ float  g_aw [(size_t)NROWS * HEADS];     // aw * 0.25
__device__ int    g_last[NN];
__device__ int    g_src [EE];
__device__ int    g_dst [EE];
__device__ int    g_bad_int;
__device__ int    g_odd_nonzero;
__device__ int    g_is_bf16;

__device__ __forceinline__ uint32_t f2tf32(float f) {
    uint32_t r;
    asm("cvt.rna.tf32.f32 %0, %1;" : "=r"(r) : "f"(f));
    return r;
}

#define CP_ASYNC16(smem_u32, gptr) \
    asm volatile("cp.async.cg.shared.global [%0], [%1], 16;" \
                 :: "r"(smem_u32), "l"(gptr))
#define CP_COMMIT() asm volatile("cp.async.commit_group;" ::: "memory")
#define CP_WAIT0()  asm volatile("cp.async.wait_group 0;" ::: "memory")

// ---------------- kernel 1: init + both dtype probes (fused) ---------------
__global__ void init_probe_kernel(float* __restrict__ out, int out_size,
                                  const unsigned* __restrict__ xw,
                                  const int* __restrict__ ew) {
    int gid = blockIdx.x * blockDim.x + threadIdx.x;
    if (gid < out_size) out[gid] = 0.0f;
    if (gid < NN)       g_last[gid] = -1;

    if (blockIdx.x == 0) {
        bool all_ok = true;
        for (int j = 0; j < 16; j++) {
            unsigned v = xw[threadIdx.x * 16 + j];
            unsigned lo = v & 0xFFFFu, hi = v >> 16;
            unsigned el = (lo >> 7) & 0xFF, eh = (hi >> 7) & 0xFF;
            bool okl = (lo & 0x7FFF) == 0 || (el >= 100 && el <= 140);
            bool okh = (hi & 0x7FFF) == 0 || (eh >= 100 && eh <= 140);
            all_ok &= (okl && okh);
        }
        int cnt = __syncthreads_count(all_ok);
        if (threadIdx.x == 0) g_is_bf16 = (cnt > 128) ? 1 : 0;
    } else if (blockIdx.x == 1) {
        bool bad = false, oddnz = false;
        for (int j = 0; j < 16; j++) {
            int i = threadIdx.x * 16 + j;
            int v = ew[i];
            if (v < 0 || v >= NN)  bad = true;
            if ((i & 1) && v != 0) oddnz = true;
        }
        int cbad = __syncthreads_count(bad);
        int codd = __syncthreads_count(oddnz);
        if (threadIdx.x == 0) {
            g_bad_int     = (cbad > 0) ? 1 : 0;
            g_odd_nonzero = (codd > 0) ? 1 : 0;
        }
    }
}

// ---------------- kernel 2: materialize W (tf32, fragment-swizzled) + a ----
// For W[n][k]: n_blk=n>>3, g=n&7, kstep=k>>3, t=k&3, h2=(k>>2)&1
//   g_wf[ ((n_blk*32 + kstep)*32 + g*4 + t)*2 + h2 ] = tf32(W[n][k])
__global__ void fconv_all_kernel(const void* __restrict__ Wraw,
                                 const void* __restrict__ araw) {
    int i = blockIdx.x * blockDim.x + threadIdx.x;
    bool bf = (g_is_bf16 != 0);
    if (i < HDIM * INF) {
        float v = bf ? __bfloat162float(((const __nv_bfloat16*)Wraw)[i])
                     : ((const float*)Wraw)[i];
        int n = i >> 8, k = i & 255;
        int n_blk = n >> 3, g = n & 7;
        int kstep = k >> 3, t = k & 3, h2 = (k >> 2) & 1;
        int dst = ((n_blk * 32 + kstep) * 32 + g * 4 + t) * 2 + h2;
        g_wf[dst] = __uint_as_float(f2tf32(v));
    } else if (i < HDIM * INF + 2 * OUTF) {
        int j = i - HDIM * INF;
        float v = bf ? __bfloat162float(((const __nv_bfloat16*)araw)[j])
                     : ((const float*)araw)[j];
        g_af[j] = v;
    }
}

// ---------------- kernel 3: convert indices + last-edge (fused) ------------
__global__ void convert_lastedge_kernel(const void* __restrict__ raw) {
    int e = blockIdx.x * blockDim.x + threadIdx.x;
    if (e >= EE) return;
    int s, d;
    if (g_bad_int) {                 // float32 layout
        const float* p = (const float*)raw;
        s = (int)p[e];  d = (int)p[EE + e];
    } else if (g_odd_nonzero) {      // int32 layout
        const int* p = (const int*)raw;
        s = p[e];       d = p[EE + e];
    } else {                         // int64 layout
        const long long* p = (const long long*)raw;
        s = (int)p[e];  d = (int)p[EE + e];
    }
    s = min(max(s, 0), NN - 1);
    d = min(max(d, 0), NN - 1);
    g_src[e] = s;
    g_dst[e] = d;
    atomicMax(&g_last[s], e);
}

// ---------------- kernel 4: pipelined tf32 GEMM, warp tile 32x64 -----------
// BM=128 x BN=128 per block, grid 313. BK=16, 2-stage cp.async (A + B).
// 8 warps: wm=warp&3 (32-row band), wn=warp>>2 (64-col half = 2 heads).
// Per 8-kstep per warp: 8 A-LDS.32 (conflict-free) + 8 B-LDS.64 -> 16 MMAs.
// Epilogue: fp16 h store + fused per-node score dots (fp32) via shfl.
#define BM 128
#define BK 16
#define AST 20    // A smem row stride: (20g+t) mod 32 all-distinct -> conflict-free
__global__ __launch_bounds__(256, 2) void gemm_tf32(const void* __restrict__ xraw) {
    __shared__ float  As[2][BM * AST];    // 2 x 10240 B
    __shared__ float2 Bs[2][1024];        // 2 x 8192 B  (total 36.9 KB)

    const int tid  = threadIdx.x;
    const int lane = tid & 31;
    const int g    = lane >> 2;        // 0..7
    const int t    = lane & 3;         // 0..3
    const int warp = tid >> 5;
    const int wm   = warp & 3;         // 32-row band
    const int wn   = warp >> 2;        // 64-col half
    const int m0   = blockIdx.x * BM;
    const bool is_bf16 = (g_is_bf16 != 0);

    const float2* gw = (const float2*)g_wf;

    float acc[2][8][4];
    #pragma unroll
    for (int i = 0; i < 2; i++)
        #pragma unroll
        for (int j = 0; j < 8; j++)
            #pragma unroll
            for (int q = 0; q < 4; q++) acc[i][j][q] = 0.0f;

    auto issue_tile = [&](int k0, int buf) {
        // B tile: 16 n_blks x 2 ksteps x 32 lanes x 8B = 8 KB, 2 chunks/thread
        #pragma unroll
        for (int p = 0; p < 2; p++) {
            int id  = tid + p * 256;
            int nb  = id >> 5;
            int rst = id & 31;
            int ksl = rst >> 4;
            int c16 = rst & 15;
            uint32_t d = (uint32_t)__cvta_generic_to_shared(
                &Bs[buf][(nb * 2 + ksl) * 32 + c16 * 2]);
            CP_ASYNC16(d, gw + ((size_t)(nb * 32 + (k0 >> 3) + ksl)) * 32 + c16 * 2);
        }
        if (!is_bf16) {
            // A tile: 128 rows x 16 floats = 8 KB, 2 chunks/thread, row-clamped
            #pragma unroll
            for (int p = 0; p < 2; p++) {
                int id = tid + p * 256;
                int r  = id >> 2;
                int c  = (id & 3) * 4;
                int row = min(m0 + r, NROWS - 1);
                uint32_t d = (uint32_t)__cvta_generic_to_shared(
                    &As[buf][r * AST + c]);
                CP_ASYNC16(d, (const float*)xraw + (size_t)row * INF + k0 + c);
            }
        } else {
            // bf16: 128 rows x 16 bf16 = 4 KB; 8 vals/thread, convert + STS
            int r  = tid >> 1;
            int c8 = (tid & 1) * 8;
            int row = min(m0 + r, NROWS - 1);
            uint4 u = *(const uint4*)((const __nv_bfloat16*)xraw +
                                      (size_t)row * INF + k0 + c8);
            const __nv_bfloat162* hb = (const __nv_bfloat162*)&u;
            float* dstp = &As[buf][r * AST + c8];
            #pragma unroll
            for (int j = 0; j < 4; j++) {
                float2 f = __bfloat1622float2(hb[j]);
                dstp[2 * j]     = f.x;
                dstp[2 * j + 1] = f.y;
            }
        }
        CP_COMMIT();
    };

    issue_tile(0, 0);
    int buf = 0;
    for (int i = 0; i < INF / BK; i++) {      // 16 iterations
        CP_WAIT0();
        __syncthreads();
        if (i < INF / BK - 1) issue_tile((i + 1) * BK, buf ^ 1);

        #pragma unroll
        for (int kk = 0; kk < 2; kk++) {      // two 8-ksteps per tile
            uint32_t a[2][4];
            #pragma unroll
            for (int mq = 0; mq < 2; mq++) {
                const float* ap =
                    &As[buf][(wm * 32 + mq * 16 + g) * AST + kk * 8 + t];
                a[mq][0] = f2tf32(ap[0]);
                a[mq][1] = f2tf32(ap[8 * AST]);
                a[mq][2] = f2tf32(ap[4]);
                a[mq][3] = f2tf32(ap[8 * AST + 4]);
            }
            #pragma unroll
            for (int nt = 0; nt < 8; nt++) {
                float2 bb = Bs[buf][((wn * 8 + nt) * 2 + kk) * 32 + lane];
                uint32_t b0 = __float_as_uint(bb.x);
                uint32_t b1 = __float_as_uint(bb.y);
                #pragma unroll
                for (int mq = 0; mq < 2; mq++) {
                    asm volatile(
                        "mma.sync.aligned.m16n8k8.row.col.f32.tf32.tf32.f32 "
                        "{%0,%1,%2,%3}, {%4,%5,%6,%7}, {%8,%9}, {%0,%1,%2,%3};"
                        : "+f"(acc[mq][nt][0]), "+f"(acc[mq][nt][1]),
                          "+f"(acc[mq][nt][2]), "+f"(acc[mq][nt][3])
                        : "r"(a[mq][0]), "r"(a[mq][1]), "r"(a[mq][2]),
                          "r"(a[mq][3]), "r"(b0), "r"(b1));
                }
            }
        }
        buf ^= 1;
    }

    // Epilogue: fp16 h + fused score dots.
    // D frag: c0=(g,2t) c1=(g,2t+1) c2=(g+8,2t) c3=(g+8,2t+1).
    float ss[2][4], sd[2][4];   // [local head][mq*2 + (0:row g, 1:row g+8)]
    #pragma unroll
    for (int i = 0; i < 2; i++)
        #pragma unroll
        for (int j = 0; j < 4; j++) { ss[i][j] = 0.f; sd[i][j] = 0.f; }

    #pragma unroll
    for (int mq = 0; mq < 2; mq++) {
        int mrow = m0 + wm * 32 + mq * 16 + g;
        #pragma unroll
        for (int nt = 0; nt < 8; nt++) {
            int hl = nt >> 2;
            int fl = (nt & 3) * 8 + 2 * t;
            int ncol = wn * 64 + nt * 8 + 2 * t;
            if (mrow < NROWS)
                *(__half2*)&g_h[(size_t)mrow * HDIM + ncol] =
                    __floats2half2_rn(acc[mq][nt][0], acc[mq][nt][1]);
            if (mrow + 8 < NROWS)
                *(__half2*)&g_h[(size_t)(mrow + 8) * HDIM + ncol] =
                    __floats2half2_rn(acc[mq][nt][2], acc[mq][nt][3]);
            float a0s = g_af[fl],        a1s = g_af[fl + 1];
            float a0d = g_af[OUTF + fl], a1d = g_af[OUTF + fl + 1];
            ss[hl][mq*2+0] += acc[mq][nt][0] * a0s + acc[mq][nt][1] * a1s;
            ss[hl][mq*2+1] += acc[mq][nt][2] * a0s + acc[mq][nt][3] * a1s;
            sd[hl][mq*2+0] += acc[mq][nt][0] * a0d + acc[mq][nt][1] * a1d;
            sd[hl][mq*2+1] += acc[mq][nt][2] * a0d + acc[mq][nt][3] * a1d;
        }
    }
    #pragma unroll
    for (int off = 1; off < 4; off <<= 1) {
        #pragma unroll
        for (int i = 0; i < 2; i++)
            #pragma unroll
            for (int j = 0; j < 4; j++) {
                ss[i][j] += __shfl_xor_sync(0xffffffffu, ss[i][j], off);
                sd[i][j] += __shfl_xor_sync(0xffffffffu, sd[i][j], off);
            }
    }
    if (t == 0) {
        #pragma unroll
        for (int hl = 0; hl < 2; hl++) {
            int head = wn * 2 + hl;
            #pragma unroll
            for (int mq = 0; mq < 2; mq++)
                #pragma unroll
                for (int rr = 0; rr < 2; rr++) {
                    int row = m0 + wm * 32 + mq * 16 + g + rr * 8;
                    if (row < NROWS) {
                        g_ssrc[row * HEADS + head] = ss[hl][mq*2+rr];
                        g_sdst[row * HEADS + head] = sd[hl][mq*2+rr];
                    }
                }
        }
    }
}

// ---------------- kernel 5: aw from last-edge softmax over batch -----------
__global__ void aw_kernel() {
    int gid = blockIdx.x * blockDim.x + threadIdx.x;   // n*HEADS + h
    if (gid >= NN * HEADS) return;
    int hh = gid & (HEADS - 1);
    int n  = gid >> 2;
    int e  = g_last[n];
    float w0 = 0.0f, w1 = 0.0f;
    if (e >= 0) {
        int d = g_dst[e];
        float z0 = g_ssrc[n * HEADS + hh]        + g_sdst[d * HEADS + hh];
        float z1 = g_ssrc[(NN + n) * HEADS + hh] + g_sdst[(NN + d) * HEADS + hh];
        z0 = z0 > 0.0f ? z0 : NEG_SLOPE * z0;
        z1 = z1 > 0.0f ? z1 : NEG_SLOPE * z1;
        float m  = fmaxf(z0, z1);
        float p0 = __expf(z0 - m);
        float p1 = __expf(z1 - m);
        float inv = 1.0f / (p0 + p1);
        w0 = p0 * inv;
        w1 = p1 * inv;
    }
    g_aw[n * HEADS + hh]        = 0.25f * w0;   // fold head-mean
    g_aw[(NN + n) * HEADS + hh] = 0.25f * w1;
}

// ---------------- kernel 6: aggregation (fp16 h), v4 RED into d_out --------
__device__ __forceinline__ void red_add_v4(float* ptr, float4 v) {
    asm volatile("red.global.add.v4.f32 [%0], {%1, %2, %3, %4};"
                 :: "l"(ptr), "f"(v.x), "f"(v.y), "f"(v.z), "f"(v.w)
                 : "memory");
}

__device__ __forceinline__ float4 ldh4(const __half* p) {
    uint2 u = __ldg((const uint2*)p);
    float2 a = __half22float2(*(__half2*)&u.x);
    float2 b = __half22float2(*(__half2*)&u.y);
    return make_float4(a.x, a.y, b.x, b.y);
}

__global__ __launch_bounds__(256) void agg_kernel(float* __restrict__ out) {
    int gid = blockIdx.x * blockDim.x + threadIdx.x;
    if (gid >= EE * BB * (OUTF / 4)) return;
    int f4 = gid & 7;          // 0..7
    int b  = (gid >> 3) & 1;
    int e  = gid >> 4;

    int src = g_src[e];
    int dst = g_dst[e];

    float4 c = *(const float4*)(g_aw + ((size_t)b * NN + src) * HEADS);

    const __half* hp = g_h + ((size_t)b * NN + dst) * HDIM + f4 * 4;
    float4 h0 = ldh4(hp);
    float4 h1 = ldh4(hp + OUTF);
    float4 h2 = ldh4(hp + 2 * OUTF);
    float4 h3 = ldh4(hp + 3 * OUTF);

    float4 v;
    v.x = c.x * h0.x + c.y * h1.x + c.z * h2.x + c.w * h3.x;
    v.y = c.x * h0.y + c.y * h1.y + c.z * h2.y + c.w * h3.y;
    v.z = c.x * h0.z + c.y * h1.z + c.z * h2.z + c.w * h3.z;
    v.w = c.x * h0.w + c.y * h1.w + c.z * h2.w + c.w * h3.w;

    red_add_v4(out + ((size_t)b * NN + src) * OUTF + f4 * 4, v);
}

// ---------------- launch ---------------------------------------------------
extern "C" void kernel_launch(void* const* d_in, const int* in_sizes, int n_in,
                              void* d_out, int out_size) {
    // Rank-based binding: largest -> x, 2nd -> edges, 3rd -> W, smallest -> a
    int order[8];
    int m = n_in < 8 ? n_in : 8;
    for (int i = 0; i < m; i++) order[i] = i;
    for (int i = 0; i < m; i++)
        for (int j = i + 1; j < m; j++)
            if (in_sizes[order[j]] > in_sizes[order[i]]) {
                int t = order[i]; order[i] = order[j]; order[j] = t;
            }
    const void* x  = d_in[m > 0 ? order[0] : 0];
    const void* ei = d_in[m > 1 ? order[1] : 1];
    const void* W  = d_in[m > 2 ? order[2] : 2];
    const void* a  = d_in[m > 3 ? order[3] : 3];

    float* out = (float*)d_out;

    {
        int n = out_size > NN ? out_size : NN;
        init_probe_kernel<<<(n + 255) / 256, 256>>>(out, out_size,
                             (const unsigned*)x, (const int*)ei);         // 1
    }
    fconv_all_kernel<<<(HDIM * INF + 2 * OUTF + 255) / 256, 256>>>(W, a); // 2
    convert_lastedge_kernel<<<(EE + 255) / 256, 256>>>(ei);               // 3
    gemm_tf32<<<(NROWS + BM - 1) / BM, 256>>>(x);                         // 4 <- profiled
    aw_kernel<<<(NN * HEADS + 255) / 256, 256>>>();                       // 5
    agg_kernel<<<(EE * BB * (OUTF / 4) + 255) / 256, 256>>>(out);         // 6
}

// round 14
// speedup vs baseline: 1.2102x; 1.0086x over previous
#include <cuda_runtime.h>
#include <cuda_bf16.h>
#include <cuda_fp16.h>
#include <cstdint>

// Problem constants (fixed shapes)
#define BB    2
#define NN    20000
#define EE    200000
#define INF   256
#define OUTF  32
#define HEADS 4
#define HDIM  (OUTF * HEADS)   // 128
#define NEG_SLOPE 0.2f
#define NROWS (BB * NN)        // 40000

// ---------------- device scratch ----------------
// CRITICAL: symbols are ONLY referenced inside device code (host-side decay of
// __device__ symbols is the GB300 ATS silent-corruption trap from rounds 1-6).
__device__ float  g_wf [HDIM * INF];                // W tf32 bits, FRAGMENT-SWIZZLED
__device__ float  g_af [2 * OUTF];                  // a (fp32)
__device__ __half g_h  [(size_t)NROWS * HDIM];      // h = x@W^T (fp16, agg-only)
__device__ float  g_ssrc[(size_t)NROWS * HEADS];    // per-node src score (fp32)
__device__ float  g_sdst[(size_t)NROWS * HEADS];    // per-node dst score (fp32)
__device__ float  g_aw [(size_t)NROWS * HEADS];     // aw * 0.25
__device__ int    g_last[NN];
__device__ int    g_src [EE];
__device__ int    g_dst [EE];
__device__ int    g_bad_int;
__device__ int    g_odd_nonzero;
__device__ int    g_is_bf16;

__device__ __forceinline__ uint32_t f2tf32(float f) {
    uint32_t r;
    asm("cvt.rna.tf32.f32 %0, %1;" : "=r"(r) : "f"(f));
    return r;
}

#define CP_ASYNC16(smem_u32, gptr) \
    asm volatile("cp.async.cg.shared.global [%0], [%1], 16;" \
                 :: "r"(smem_u32), "l"(gptr))
#define CP_COMMIT()  asm volatile("cp.async.commit_group;" ::: "memory")
#define CP_WAIT(n)   asm volatile("cp.async.wait_group %0;" :: "n"(n) : "memory")

// ---------------- kernel 1: init + both dtype probes (fused) ---------------
__global__ void init_probe_kernel(float* __restrict__ out, int out_size,
                                  const unsigned* __restrict__ xw,
                                  const int* __restrict__ ew) {
    int gid = blockIdx.x * blockDim.x + threadIdx.x;
    if (gid < out_size) out[gid] = 0.0f;
    if (gid < NN)       g_last[gid] = -1;

    if (blockIdx.x == 0) {
        bool all_ok = true;
        for (int j = 0; j < 16; j++) {
            unsigned v = xw[threadIdx.x * 16 + j];
            unsigned lo = v & 0xFFFFu, hi = v >> 16;
            unsigned el = (lo >> 7) & 0xFF, eh = (hi >> 7) & 0xFF;
            bool okl = (lo & 0x7FFF) == 0 || (el >= 100 && el <= 140);
            bool okh = (hi & 0x7FFF) == 0 || (eh >= 100 && eh <= 140);
            all_ok &= (okl && okh);
        }
        int cnt = __syncthreads_count(all_ok);
        if (threadIdx.x == 0) g_is_bf16 = (cnt > 128) ? 1 : 0;
    } else if (blockIdx.x == 1) {
        bool bad = false, oddnz = false;
        for (int j = 0; j < 16; j++) {
            int i = threadIdx.x * 16 + j;
            int v = ew[i];
            if (v < 0 || v >= NN)  bad = true;
            if ((i & 1) && v != 0) oddnz = true;
        }
        int cbad = __syncthreads_count(bad);
        int codd = __syncthreads_count(oddnz);
        if (threadIdx.x == 0) {
            g_bad_int     = (cbad > 0) ? 1 : 0;
            g_odd_nonzero = (codd > 0) ? 1 : 0;
        }
    }
}

// ---------------- kernel 2: materialize W (tf32, fragment-swizzled) + a ----
// For W[n][k]: n_blk=n>>3, g=n&7, kstep=k>>3, t=k&3, h2=(k>>2)&1
//   g_wf[ ((n_blk*32 + kstep)*32 + g*4 + t)*2 + h2 ] = tf32(W[n][k])
__global__ void fconv_all_kernel(const void* __restrict__ Wraw,
                                 const void* __restrict__ araw) {
    int i = blockIdx.x * blockDim.x + threadIdx.x;
    bool bf = (g_is_bf16 != 0);
    if (i < HDIM * INF) {
        float v = bf ? __bfloat162float(((const __nv_bfloat16*)Wraw)[i])
                     : ((const float*)Wraw)[i];
        int n = i >> 8, k = i & 255;
        int n_blk = n >> 3, g = n & 7;
        int kstep = k >> 3, t = k & 3, h2 = (k >> 2) & 1;
        int dst = ((n_blk * 32 + kstep) * 32 + g * 4 + t) * 2 + h2;
        g_wf[dst] = __uint_as_float(f2tf32(v));
    } else if (i < HDIM * INF + 2 * OUTF) {
        int j = i - HDIM * INF;
        float v = bf ? __bfloat162float(((const __nv_bfloat16*)araw)[j])
                     : ((const float*)araw)[j];
        g_af[j] = v;
    }
}

// ---------------- kernel 3: convert indices + last-edge (fused) ------------
__global__ void convert_lastedge_kernel(const void* __restrict__ raw) {
    int e = blockIdx.x * blockDim.x + threadIdx.x;
    if (e >= EE) return;
    int s, d;
    if (g_bad_int) {                 // float32 layout
        const float* p = (const float*)raw;
        s = (int)p[e];  d = (int)p[EE + e];
    } else if (g_odd_nonzero) {      // int32 layout
        const int* p = (const int*)raw;
        s = p[e];       d = p[EE + e];
    } else {                         // int64 layout
        const long long* p = (const long long*)raw;
        s = (int)p[e];  d = (int)p[EE + e];
    }
    s = min(max(s, 0), NN - 1);
    d = min(max(d, 0), NN - 1);
    g_src[e] = s;
    g_dst[e] = d;
    atomicMax(&g_last[s], e);
}

// ---------------- kernel 4: 4-stage BK=8 tf32 GEMM ------------------------
// BM=128 x BN=128 per block, grid 313. 4-stage cp.async, wait_group 2 ->
// 3 tiles of prefetch distance. 8 warps, warp tile 32x64.
// Per iteration per warp: 8 A-LDS.32 + 8 B-LDS.64 -> 16 MMAs.
// Epilogue: fp16 h store + fused per-node score dots (fp32) via shfl.
#define BM 128
#define BK 8
#define NSTAGE 4
#define AST8 12   // (12g+t) mod 32 bijective over warp -> conflict-free
__global__ __launch_bounds__(256, 2) void gemm_tf32(const void* __restrict__ xraw) {
    __shared__ float  As[NSTAGE][BM * AST8];   // 4 x 6144 B
    __shared__ float2 Bs[NSTAGE][512];         // 4 x 4096 B  (total 40 KB)

    const int tid  = threadIdx.x;
    const int lane = tid & 31;
    const int g    = lane >> 2;        // 0..7
    const int t    = lane & 3;         // 0..3
    const int warp = tid >> 5;
    const int wm   = warp & 3;         // 32-row band
    const int wn   = warp >> 2;        // 64-col half
    const int m0   = blockIdx.x * BM;
    const bool is_bf16 = (g_is_bf16 != 0);

    const float2* gw = (const float2*)g_wf;

    float acc[2][8][4];
    #pragma unroll
    for (int i = 0; i < 2; i++)
        #pragma unroll
        for (int j = 0; j < 8; j++)
            #pragma unroll
            for (int q = 0; q < 4; q++) acc[i][j][q] = 0.0f;

    auto issue_tile = [&](int kstep, int buf) {
        // B tile: 16 n_blks x 32 lanes x 8B = 4 KB, one chunk per thread
        {
            int nb  = tid >> 4;            // 0..15
            int c16 = tid & 15;            // 0..15 (pairs of float2)
            uint32_t d = (uint32_t)__cvta_generic_to_shared(
                &Bs[buf][nb * 32 + c16 * 2]);
            CP_ASYNC16(d, gw + ((size_t)(nb * 32 + kstep)) * 32 + c16 * 2);
        }
        if (!is_bf16) {
            // A tile: 128 rows x 8 floats = 4 KB, one chunk per thread
            int r = tid >> 1;
            int c = (tid & 1) * 4;
            int row = min(m0 + r, NROWS - 1);
            uint32_t d = (uint32_t)__cvta_generic_to_shared(
                &As[buf][r * AST8 + c]);
            CP_ASYNC16(d, (const float*)xraw + (size_t)row * INF + kstep * 8 + c);
        } else {
            // bf16: 128 rows x 8 bf16 = 2 KB; threads 0..127, one uint4 each
            if (tid < BM) {
                int row = min(m0 + tid, NROWS - 1);
                uint4 u = *(const uint4*)((const __nv_bfloat16*)xraw +
                                          (size_t)row * INF + kstep * 8);
                const __nv_bfloat162* hb = (const __nv_bfloat162*)&u;
                float* dstp = &As[buf][tid * AST8];
                #pragma unroll
                for (int j = 0; j < 4; j++) {
                    float2 f = __bfloat1622float2(hb[j]);
                    dstp[2 * j]     = f.x;
                    dstp[2 * j + 1] = f.y;
                }
            }
        }
        CP_COMMIT();
    };

    issue_tile(0, 0);
    issue_tile(1, 1);
    issue_tile(2, 2);

    #pragma unroll 4
    for (int i = 0; i < INF / BK; i++) {      // 32 iterations
        CP_WAIT(2);                           // tile i resident
        __syncthreads();
        if (i + 3 < INF / BK) issue_tile(i + 3, (i + 3) & (NSTAGE - 1));

        int buf = i & (NSTAGE - 1);
        uint32_t a[2][4];
        #pragma unroll
        for (int mq = 0; mq < 2; mq++) {
            const float* ap = &As[buf][(wm * 32 + mq * 16 + g) * AST8 + t];
            a[mq][0] = f2tf32(ap[0]);
            a[mq][1] = f2tf32(ap[8 * AST8]);
            a[mq][2] = f2tf32(ap[4]);
            a[mq][3] = f2tf32(ap[8 * AST8 + 4]);
        }
        #pragma unroll
        for (int nt = 0; nt < 8; nt++) {
            float2 bb = Bs[buf][(wn * 8 + nt) * 32 + lane];
            uint32_t b0 = __float_as_uint(bb.x);
            uint32_t b1 = __float_as_uint(bb.y);
            #pragma unroll
            for (int mq = 0; mq < 2; mq++) {
                asm volatile(
                    "mma.sync.aligned.m16n8k8.row.col.f32.tf32.tf32.f32 "
                    "{%0,%1,%2,%3}, {%4,%5,%6,%7}, {%8,%9}, {%0,%1,%2,%3};"
                    : "+f"(acc[mq][nt][0]), "+f"(acc[mq][nt][1]),
                      "+f"(acc[mq][nt][2]), "+f"(acc[mq][nt][3])
                    : "r"(a[mq][0]), "r"(a[mq][1]), "r"(a[mq][2]),
                      "r"(a[mq][3]), "r"(b0), "r"(b1));
            }
        }
        __syncthreads();   // all warps done with buf before it is refilled
    }

    // Epilogue: fp16 h + fused score dots.
    // D frag: c0=(g,2t) c1=(g,2t+1) c2=(g+8,2t) c3=(g+8,2t+1).
    float ss[2][4], sd[2][4];   // [local head][mq*2 + (0:row g, 1:row g+8)]
    #pragma unroll
    for (int i = 0; i < 2; i++)
        #pragma unroll
        for (int j = 0; j < 4; j++) { ss[i][j] = 0.f; sd[i][j] = 0.f; }

    #pragma unroll
    for (int mq = 0; mq < 2; mq++) {
        int mrow = m0 + wm * 32 + mq * 16 + g;
        #pragma unroll
        for (int nt = 0; nt < 8; nt++) {
            int hl = nt >> 2;
            int fl = (nt & 3) * 8 + 2 * t;
            int ncol = wn * 64 + nt * 8 + 2 * t;
            if (mrow < NROWS)
                *(__half2*)&g_h[(size_t)mrow * HDIM + ncol] =
                    __floats2half2_rn(acc[mq][nt][0], acc[mq][nt][1]);
            if (mrow + 8 < NROWS)
                *(__half2*)&g_h[(size_t)(mrow + 8) * HDIM + ncol] =
                    __floats2half2_rn(acc[mq][nt][2], acc[mq][nt][3]);
            float a0s = g_af[fl],        a1s = g_af[fl + 1];
            float a0d = g_af[OUTF + fl], a1d = g_af[OUTF + fl + 1];
            ss[hl][mq*2+0] += acc[mq][nt][0] * a0s + acc[mq][nt][1] * a1s;
            ss[hl][mq*2+1] += acc[mq][nt][2] * a0s + acc[mq][nt][3] * a1s;
            sd[hl][mq*2+0] += acc[mq][nt][0] * a0d + acc[mq][nt][1] * a1d;
            sd[hl][mq*2+1] += acc[mq][nt][2] * a0d + acc[mq][nt][3] * a1d;
        }
    }
    #pragma unroll
    for (int off = 1; off < 4; off <<= 1) {
        #pragma unroll
        for (int i = 0; i < 2; i++)
            #pragma unroll
            for (int j = 0; j < 4; j++) {
                ss[i][j] += __shfl_xor_sync(0xffffffffu, ss[i][j], off);
                sd[i][j] += __shfl_xor_sync(0xffffffffu, sd[i][j], off);
            }
    }
    if (t == 0) {
        #pragma unroll
        for (int hl = 0; hl < 2; hl++) {
            int head = wn * 2 + hl;
            #pragma unroll
            for (int mq = 0; mq < 2; mq++)
                #pragma unroll
                for (int rr = 0; rr < 2; rr++) {
                    int row = m0 + wm * 32 + mq * 16 + g + rr * 8;
                    if (row < NROWS) {
                        g_ssrc[row * HEADS + head] = ss[hl][mq*2+rr];
                        g_sdst[row * HEADS + head] = sd[hl][mq*2+rr];
                    }
                }
        }
    }
}

// ---------------- kernel 5: aw from last-edge softmax over batch -----------
__global__ void aw_kernel() {
    int gid = blockIdx.x * blockDim.x + threadIdx.x;   // n*HEADS + h
    if (gid >= NN * HEADS) return;
    int hh = gid & (HEADS - 1);
    int n  = gid >> 2;
    int e  = g_last[n];
    float w0 = 0.0f, w1 = 0.0f;
    if (e >= 0) {
        int d = g_dst[e];
        float z0 = g_ssrc[n * HEADS + hh]        + g_sdst[d * HEADS + hh];
        float z1 = g_ssrc[(NN + n) * HEADS + hh] + g_sdst[(NN + d) * HEADS + hh];
        z0 = z0 > 0.0f ? z0 : NEG_SLOPE * z0;
        z1 = z1 > 0.0f ? z1 : NEG_SLOPE * z1;
        float m  = fmaxf(z0, z1);
        float p0 = __expf(z0 - m);
        float p1 = __expf(z1 - m);
        float inv = 1.0f / (p0 + p1);
        w0 = p0 * inv;
        w1 = p1 * inv;
    }
    g_aw[n * HEADS + hh]        = 0.25f * w0;   // fold head-mean
    g_aw[(NN + n) * HEADS + hh] = 0.25f * w1;
}

// ---------------- kernel 6: aggregation (fp16 h), v4 RED into d_out --------
__device__ __forceinline__ void red_add_v4(float* ptr, float4 v) {
    asm volatile("red.global.add.v4.f32 [%0], {%1, %2, %3, %4};"
                 :: "l"(ptr), "f"(v.x), "f"(v.y), "f"(v.z), "f"(v.w)
                 : "memory");
}

__device__ __forceinline__ float4 ldh4(const __half* p) {
    uint2 u = __ldg((const uint2*)p);
    float2 a = __half22float2(*(__half2*)&u.x);
    float2 b = __half22float2(*(__half2*)&u.y);
    return make_float4(a.x, a.y, b.x, b.y);
}

__global__ __launch_bounds__(256) void agg_kernel(float* __restrict__ out) {
    int gid = blockIdx.x * blockDim.x + threadIdx.x;
    if (gid >= EE * BB * (OUTF / 4)) return;
    int f4 = gid & 7;          // 0..7
    int b  = (gid >> 3) & 1;
    int e  = gid >> 4;

    int src = g_src[e];
    int dst = g_dst[e];

    float4 c = *(const float4*)(g_aw + ((size_t)b * NN + src) * HEADS);

    const __half* hp = g_h + ((size_t)b * NN + dst) * HDIM + f4 * 4;
    float4 h0 = ldh4(hp);
    float4 h1 = ldh4(hp + OUTF);
    float4 h2 = ldh4(hp + 2 * OUTF);
    float4 h3 = ldh4(hp + 3 * OUTF);

    float4 v;
    v.x = c.x * h0.x + c.y * h1.x + c.z * h2.x + c.w * h3.x;
    v.y = c.x * h0.y + c.y * h1.y + c.z * h2.y + c.w * h3.y;
    v.z = c.x * h0.z + c.y * h1.z + c.z * h2.z + c.w * h3.z;
    v.w = c.x * h0.w + c.y * h1.w + c.z * h2.w + c.w * h3.w;

    red_add_v4(out + ((size_t)b * NN + src) * OUTF + f4 * 4, v);
}

// ---------------- launch ---------------------------------------------------
extern "C" void kernel_launch(void* const* d_in, const int* in_sizes, int n_in,
                              void* d_out, int out_size) {
    // Rank-based binding: largest -> x, 2nd -> edges, 3rd -> W, smallest -> a
    int order[8];
    int m = n_in < 8 ? n_in : 8;
    for (int i = 0; i < m; i++) order[i] = i;
    for (int i = 0; i < m; i++)
        for (int j = i + 1; j < m; j++)
            if (in_sizes[order[j]] > in_sizes[order[i]]) {
                int t = order[i]; order[i] = order[j]; order[j] = t;
            }
    const void* x  = d_in[m > 0 ? order[0] : 0];
    const void* ei = d_in[m > 1 ? order[1] : 1];
    const void* W  = d_in[m > 2 ? order[2] : 2];
    const void* a  = d_in[m > 3 ? order[3] : 3];

    float* out = (float*)d_out;

    {
        int n = out_size > NN ? out_size : NN;
        init_probe_kernel<<<(n + 255) / 256, 256>>>(out, out_size,
                             (const unsigned*)x, (const int*)ei);         // 1
    }
    fconv_all_kernel<<<(HDIM * INF + 2 * OUTF + 255) / 256, 256>>>(W, a); // 2
    convert_lastedge_kernel<<<(EE + 255) / 256, 256>>>(ei);               // 3
    gemm_tf32<<<(NROWS + BM - 1) / BM, 256>>>(x);                         // 4 <- profiled
    aw_kernel<<<(NN * HEADS + 255) / 256, 256>>>();                       // 5
    agg_kernel<<<(EE * BB * (OUTF / 4) + 255) / 256, 256>>>(out);         // 6
}